// round 9
// baseline (speedup 1.0000x reference)
#include <cuda_runtime.h>
#include <math.h>

#define N_USERS 100000
#define N_ITEMS 50000
#define NNZ     1600000
#define NB      64
#define ORDER   8

#define NBLK_U  98   // ceil(100000/1024)
#define NBLK_I  49   // ceil(50000/1024)
#define NBLK_T  (NBLK_U + NBLK_I)   // 147

// ---------------- scratch (static device memory; no allocations) ----------------
__device__ float g_T[(size_t)(ORDER + 1) * N_ITEMS * NB];   // scaled T_0 .. T_8
__device__ float g_Y[(size_t)N_USERS * NB];
__device__ int   g_ecolR[NNZ];           // row(user)-sorted: col index only
__device__ int   g_erowC[NNZ];           // col(item)-sorted: row index only
__device__ int   g_rowptr[N_USERS + 1];
__device__ int   g_colptr[N_ITEMS + 1];
__device__ int   g_pos[N_USERS + N_ITEMS];  // counts -> write cursors
__device__ int   g_part[NBLK_T];
__device__ int   g_choff[NBLK_T];
__device__ float g_du_inv[N_USERS];      // du>0 ? 1/du : 0
__device__ float g_di_inv[N_ITEMS];      // di>0 ? 1/di : 0
__device__ float g_di_is[N_ITEMS];       // di>0 ? di^-1/2 : 0
__device__ float g_fin_a[N_ITEMS];       // di>0 ? di^+1/2 : 0
__device__ float g_fin_b[N_ITEMS];       // di>0 ? 0 : sum(c_k)

struct Coeffs { float c[ORDER + 1]; };

// ---------------- CSR build ----------------
__global__ void k_hist(const int4* __restrict__ row4, const int4* __restrict__ col4,
                       int* __restrict__ pos) {
    int e = blockIdx.x * blockDim.x + threadIdx.x;
    if (e < NNZ / 4) {
        int4 r = __ldg(&row4[e]);
        int4 c = __ldg(&col4[e]);
        atomicAdd(&pos[r.x], 1);
        atomicAdd(&pos[r.y], 1);
        atomicAdd(&pos[r.z], 1);
        atomicAdd(&pos[r.w], 1);
        atomicAdd(&pos[N_USERS + c.x], 1);
        atomicAdd(&pos[N_USERS + c.y], 1);
        atomicAdd(&pos[N_USERS + c.z], 1);
        atomicAdd(&pos[N_USERS + c.w], 1);
    }
}

// combined per-chunk sums for both segments (147 blocks, shuffle reduce)
__global__ void k_chunksum(const int* __restrict__ pos, int* __restrict__ part) {
    __shared__ int wsum[32];
    int t = threadIdx.x;
    int b = blockIdx.x;
    int local, gbase, n;
    if (b < NBLK_U) { local = b * 1024 + t;            gbase = 0;       n = N_USERS; }
    else            { local = (b - NBLK_U) * 1024 + t; gbase = N_USERS; n = N_ITEMS; }
    int v = (local < n) ? pos[gbase + local] : 0;
#pragma unroll
    for (int o = 16; o > 0; o >>= 1) v += __shfl_down_sync(0xffffffffu, v, o);
    if ((t & 31) == 0) wsum[t >> 5] = v;
    __syncthreads();
    if (t < 32) {
        int x = wsum[t];
#pragma unroll
        for (int o = 16; o > 0; o >>= 1) x += __shfl_down_sync(0xffffffffu, x, o);
        if (t == 0) part[b] = x;
    }
}

// scan chunk sums: segment U = part[0..97], segment I = part[98..146]
__global__ void k_scanpart(const int* __restrict__ part, int* __restrict__ choff) {
    __shared__ int s[128];
    int t = threadIdx.x;
    int v = (t < NBLK_U) ? part[t] : 0;
    s[t] = v;
    __syncthreads();
    for (int o = 1; o < 128; o <<= 1) {
        int a = (t >= o) ? s[t - o] : 0;
        __syncthreads();
        s[t] += a;
        __syncthreads();
    }
    if (t < NBLK_U) choff[t] = s[t] - v;  // exclusive
    __syncthreads();
    v = (t < NBLK_I) ? part[NBLK_U + t] : 0;
    s[t] = v;
    __syncthreads();
    for (int o = 1; o < 128; o <<= 1) {
        int a = (t >= o) ? s[t - o] : 0;
        __syncthreads();
        s[t] += a;
        __syncthreads();
    }
    if (t < NBLK_I) choff[NBLK_U + t] = s[t] - v;
}

// per-chunk exclusive scan (shuffle) -> ptr, cursor, degree-scale tables
__global__ void k_scanchunk(int* __restrict__ pos, const int* __restrict__ choff,
                            int* __restrict__ rptr, int* __restrict__ cptr,
                            float* __restrict__ du_inv, float* __restrict__ di_inv,
                            float* __restrict__ di_is,
                            float* __restrict__ fin_a, float* __restrict__ fin_b,
                            float csum) {
    __shared__ int wsum[32];
    int t = threadIdx.x;
    int b = blockIdx.x;
    int lane = t & 31;
    int wid = t >> 5;
    int local, n, gidx;
    int* ptr;
    bool isU = (b < NBLK_U);
    if (isU) {
        local = b * 1024 + t;             n = N_USERS;  gidx = local;            ptr = rptr;
    } else {
        local = (b - NBLK_U) * 1024 + t;  n = N_ITEMS;  gidx = N_USERS + local;  ptr = cptr;
    }
    int v = (local < n) ? pos[gidx] : 0;
    // inclusive warp scan
    int x = v;
#pragma unroll
    for (int o = 1; o < 32; o <<= 1) {
        int y = __shfl_up_sync(0xffffffffu, x, o);
        if (lane >= o) x += y;
    }
    if (lane == 31) wsum[wid] = x;
    __syncthreads();
    if (t < 32) {
        int y = wsum[t];
#pragma unroll
        for (int o = 1; o < 32; o <<= 1) {
            int z = __shfl_up_sync(0xffffffffu, y, o);
            if (t >= o) y += z;
        }
        wsum[t] = y;
    }
    __syncthreads();
    int incl = x + (wid > 0 ? wsum[wid - 1] : 0);
    if (local < n) {
        int ex = choff[b] + incl - v;   // exclusive prefix
        ptr[local] = ex;
        pos[gidx] = ex;                 // scatter cursor
        if (isU) {
            du_inv[local] = (v > 0) ? (1.0f / (float)v) : 0.f;
        } else {
            if (v > 0) {
                float fv = (float)v;
                float sq = sqrtf(fv);
                di_inv[local] = 1.0f / fv;
                di_is[local]  = 1.0f / sq;
                fin_a[local]  = sq;
                fin_b[local]  = 0.f;
            } else {
                di_inv[local] = 0.f;
                di_is[local]  = 0.f;
                fin_a[local]  = 0.f;
                fin_b[local]  = csum;
            }
        }
    }
    if (local == 0) ptr[n] = NNZ;
}

__global__ void k_scatter(const int4* __restrict__ row4, const int4* __restrict__ col4,
                          int* __restrict__ pos,
                          int* __restrict__ ecolR, int* __restrict__ erowC) {
    int e = blockIdx.x * blockDim.x + threadIdx.x;
    if (e < NNZ / 4) {
        int4 r = __ldg(&row4[e]);
        int4 c = __ldg(&col4[e]);
        int p;
        p = atomicAdd(&pos[r.x], 1); ecolR[p] = c.x;
        p = atomicAdd(&pos[r.y], 1); ecolR[p] = c.y;
        p = atomicAdd(&pos[r.z], 1); ecolR[p] = c.z;
        p = atomicAdd(&pos[r.w], 1); ecolR[p] = c.w;
        p = atomicAdd(&pos[N_USERS + c.x], 1); erowC[p] = r.x;
        p = atomicAdd(&pos[N_USERS + c.y], 1); erowC[p] = r.y;
        p = atomicAdd(&pos[N_USERS + c.z], 1); erowC[p] = r.z;
        p = atomicAdd(&pos[N_USERS + c.w], 1); erowC[p] = r.w;
    }
}

// ---------------- transpose in: T0[i][b] = di_is[i] * signal[b][i] ----------------
__global__ void k_transpose_in(const float* __restrict__ src, float* __restrict__ dst,
                               const float* __restrict__ di_is) {
    __shared__ float tile[32][33];
    int i0 = blockIdx.x * 32, b0 = blockIdx.y * 32;
    int x = threadIdx.x;
    for (int ty = threadIdx.y; ty < 32; ty += 8) {
        int b = b0 + ty, i = i0 + x;
        tile[ty][x] = (i < N_ITEMS) ? src[(long)b * N_ITEMS + i] : 0.f;
    }
    __syncthreads();
    for (int ty = threadIdx.y; ty < 32; ty += 8) {
        int i = i0 + ty, b = b0 + x;
        if (i < N_ITEMS) dst[(long)i * NB + b] = __ldg(&di_is[i]) * tile[x][ty];
    }
}

// ---- finalize: out[b][i] = fin_a[i] * sum_k c_k T_k[i][b] + fin_b[i]*signal[b][i] ----
__global__ void k_finalize(const float* __restrict__ T, const float* __restrict__ sig,
                           float* __restrict__ dst,
                           const float* __restrict__ fin_a, const float* __restrict__ fin_b,
                           Coeffs C) {
    __shared__ float tile[32][33];
    int i0 = blockIdx.x * 32, b0 = blockIdx.y * 32;
    int x = threadIdx.x;
    const long stride = (long)N_ITEMS * NB;
    for (int ty = threadIdx.y; ty < 32; ty += 8) {
        int i = i0 + ty, b = b0 + x;
        float acc = 0.f;
        if (i < N_ITEMS) {
            long off = (long)i * NB + b;
#pragma unroll
            for (int k = 0; k <= ORDER; k++)
                acc += C.c[k] * __ldg(&T[off + (long)k * stride]);
            acc *= __ldg(&fin_a[i]);
        }
        tile[ty][x] = acc;
    }
    __syncthreads();
    for (int ty = threadIdx.y; ty < 32; ty += 8) {
        int b = b0 + ty, i = i0 + x;
        if (i < N_ITEMS)
            dst[(long)b * N_ITEMS + i] =
                tile[x][ty] + __ldg(&fin_b[i]) * __ldg(&sig[(long)b * N_ITEMS + i]);
    }
}

// ---------------- hot loop: unweighted gather SpMM (no atomics) ----------------
// y'[u][:] = du_inv[u] * sum_{e in row u} x[col[e]][:]
__global__ void __launch_bounds__(256)
k_gather_y(const int* __restrict__ ecol, const int* __restrict__ ptr,
           const float* __restrict__ X, float* __restrict__ Y,
           const float* __restrict__ du_inv, int nrows) {
    int warp = (blockIdx.x * blockDim.x + threadIdx.x) >> 5;
    int lane = threadIdx.x & 31;
    if (warp >= nrows) return;
    int s = __ldg(&ptr[warp]);
    int e = __ldg(&ptr[warp + 1]);
    const float2* X2 = (const float2*)X;
    float2 a0 = make_float2(0.f, 0.f), a1 = a0, a2 = a0, a3 = a0;
    int j = s;
    for (; j + 4 <= e; j += 4) {
        int c0 = __ldg(&ecol[j]);
        int c1 = __ldg(&ecol[j + 1]);
        int c2 = __ldg(&ecol[j + 2]);
        int c3 = __ldg(&ecol[j + 3]);
        float2 x0 = __ldg(X2 + (((long)c0 << 5) + lane));
        float2 x1 = __ldg(X2 + (((long)c1 << 5) + lane));
        float2 x2 = __ldg(X2 + (((long)c2 << 5) + lane));
        float2 x3 = __ldg(X2 + (((long)c3 << 5) + lane));
        a0.x += x0.x; a0.y += x0.y;
        a1.x += x1.x; a1.y += x1.y;
        a2.x += x2.x; a2.y += x2.y;
        a3.x += x3.x; a3.y += x3.y;
    }
    for (; j < e; ++j) {
        float2 xv = __ldg(X2 + (((long)__ldg(&ecol[j]) << 5) + lane));
        a0.x += xv.x; a0.y += xv.y;
    }
    float sc = __ldg(&du_inv[warp]);
    float2 r;
    r.x = sc * (a0.x + a1.x + a2.x + a3.x);
    r.y = sc * (a0.y + a1.y + a2.y + a3.y);
    ((float2*)Y)[((long)warp << 5) + lane] = r;
}

// v[i] = sum_{e in col i} y'[row[e]] ;  t_new = ax*x + az*di_inv[i]*v + at*t_old
__global__ void __launch_bounds__(256)
k_z_fused(const int* __restrict__ erow, const int* __restrict__ ptr,
          const float* __restrict__ Y, const float* __restrict__ X,
          const float* __restrict__ Told, float* __restrict__ Tnew,
          const float* __restrict__ di_inv,
          float ax, float az, float at) {
    int warp = (blockIdx.x * blockDim.x + threadIdx.x) >> 5;
    int lane = threadIdx.x & 31;
    if (warp >= N_ITEMS) return;
    int s = __ldg(&ptr[warp]);
    int e = __ldg(&ptr[warp + 1]);
    const float2* Y2 = (const float2*)Y;
    float2 a0 = make_float2(0.f, 0.f), a1 = a0, a2 = a0, a3 = a0;
    int j = s;
    for (; j + 4 <= e; j += 4) {
        int r0 = __ldg(&erow[j]);
        int r1 = __ldg(&erow[j + 1]);
        int r2 = __ldg(&erow[j + 2]);
        int r3 = __ldg(&erow[j + 3]);
        float2 y0 = __ldg(Y2 + (((long)r0 << 5) + lane));
        float2 y1 = __ldg(Y2 + (((long)r1 << 5) + lane));
        float2 y2 = __ldg(Y2 + (((long)r2 << 5) + lane));
        float2 y3 = __ldg(Y2 + (((long)r3 << 5) + lane));
        a0.x += y0.x; a0.y += y0.y;
        a1.x += y1.x; a1.y += y1.y;
        a2.x += y2.x; a2.y += y2.y;
        a3.x += y3.x; a3.y += y3.y;
    }
    for (; j < e; ++j) {
        float2 yv = __ldg(Y2 + (((long)__ldg(&erow[j]) << 5) + lane));
        a0.x += yv.x; a0.y += yv.y;
    }
    float azz = az * __ldg(&di_inv[warp]);
    float2 zz;
    zz.x = azz * (a0.x + a1.x + a2.x + a3.x);
    zz.y = azz * (a0.y + a1.y + a2.y + a3.y);
    long base = ((long)warp << 5) + lane;
    float2 xv = __ldg((const float2*)X + base);
    float2 tv = __ldg((const float2*)Told + base);
    float2 tn;
    tn.x = ax * xv.x + zz.x + at * tv.x;
    tn.y = ax * xv.y + zz.y + at * tv.y;
    ((float2*)Tnew)[base] = tn;
}

// ---------------- host ----------------
static void compute_coeffs(double* c) {
    const double PI = 3.14159265358979323846;
    auto r3 = [](double v) { return nearbyint(v * 1000.0) / 1000.0; };
    double tgt[ORDER + 1], nodes[ORDER + 1];
    for (int x = 0; x <= ORDER; x++) {
        double xv = r3(cos((double)(ORDER - x) / ORDER * PI));
        double t = (xv < 0.0) ? (xv * xv * 0.5 + 0.5) : (xv * xv * (-0.5) + 0.5);
        tgt[x] = r3(t);
    }
    for (int k = 1; k <= ORDER + 1; k++)
        nodes[k - 1] = cos((ORDER + 1 + 0.5 - (double)k) / (ORDER + 1) * PI);
    double Tm2[ORDER + 1], Tm1[ORDER + 1];
    double s0 = 0.0, s1 = 0.0;
    for (int j = 0; j <= ORDER; j++) {
        Tm2[j] = tgt[j];
        Tm1[j] = nodes[j] * tgt[j];
        s0 += Tm2[j];
        s1 += Tm1[j];
    }
    double sc = 2.0 / (ORDER + 1);
    c[0] = s0 * sc / 2.0;
    c[1] = s1 * sc;
    for (int k = 2; k <= ORDER; k++) {
        double sum = 0.0;
        for (int j = 0; j <= ORDER; j++) {
            double t = 2.0 * nodes[j] * Tm1[j] - Tm2[j];
            Tm2[j] = Tm1[j];
            Tm1[j] = t;
            sum += t;
        }
        c[k] = sum * sc;
    }
}

extern "C" void kernel_launch(void* const* d_in, const int* in_sizes, int n_in,
                              void* d_out, int out_size) {
    const float* signal = (const float*)d_in[0];
    const int*   row    = (const int*)d_in[2];
    const int*   col    = (const int*)d_in[3];
    float* outp = (float*)d_out;

    double c[ORDER + 1];
    compute_coeffs(c);
    Coeffs C;
    double cs = 0.0;
    for (int k = 0; k <= ORDER; k++) { C.c[k] = (float)c[k]; cs += c[k]; }
    float csum = (float)cs;

    float *T, *Y, *du_inv, *di_inv, *di_is, *fin_a, *fin_b;
    int *ecolR, *erowC, *rptr, *cptr, *pos, *part, *choff;
    cudaGetSymbolAddress((void**)&T, g_T);
    cudaGetSymbolAddress((void**)&Y, g_Y);
    cudaGetSymbolAddress((void**)&ecolR, g_ecolR);
    cudaGetSymbolAddress((void**)&erowC, g_erowC);
    cudaGetSymbolAddress((void**)&rptr, g_rowptr);
    cudaGetSymbolAddress((void**)&cptr, g_colptr);
    cudaGetSymbolAddress((void**)&pos, g_pos);
    cudaGetSymbolAddress((void**)&part, g_part);
    cudaGetSymbolAddress((void**)&choff, g_choff);
    cudaGetSymbolAddress((void**)&du_inv, g_du_inv);
    cudaGetSymbolAddress((void**)&di_inv, g_di_inv);
    cudaGetSymbolAddress((void**)&di_is, g_di_is);
    cudaGetSymbolAddress((void**)&fin_a, g_fin_a);
    cudaGetSymbolAddress((void**)&fin_b, g_fin_b);

    const long TSZ = (long)N_ITEMS * NB;

    // ----- build both CSRs + degree tables -----
    cudaMemsetAsync(pos, 0, (N_USERS + N_ITEMS) * sizeof(int));
    k_hist<<<(NNZ / 4 + 255) / 256, 256>>>((const int4*)row, (const int4*)col, pos);
    k_chunksum<<<NBLK_T, 1024>>>(pos, part);
    k_scanpart<<<1, 128>>>(part, choff);
    k_scanchunk<<<NBLK_T, 1024>>>(pos, choff, rptr, cptr,
                                  du_inv, di_inv, di_is, fin_a, fin_b, csum);
    k_scatter<<<(NNZ / 4 + 255) / 256, 256>>>((const int4*)row, (const int4*)col,
                                              pos, ecolR, erowC);

    // ----- transpose + prescale: T0 = D_i^{-1/2} signal^T -----
    k_transpose_in<<<dim3((N_ITEMS + 31) / 32, 2), dim3(32, 8)>>>(signal, T, di_is);

    const int GY = (N_USERS * 32 + 255) / 256;  // warp per user row
    const int GZ = (N_ITEMS * 32 + 255) / 256;  // warp per item row

    // lap 1: T1 = T0 - 2 z(T0)
    k_gather_y<<<GY, 256>>>(ecolR, rptr, T, Y, du_inv, N_USERS);
    k_z_fused<<<GZ, 256>>>(erowC, cptr, Y, T, T, T + TSZ, di_inv, 1.f, -2.f, 0.f);

    // laps k=2..8: Tk = 2*T_{k-1} - 4 z(T_{k-1}) - T_{k-2}
    for (int k = 2; k <= ORDER; k++) {
        const float* t1 = T + (long)(k - 1) * TSZ;
        const float* t0 = T + (long)(k - 2) * TSZ;
        float* tn = T + (long)k * TSZ;
        k_gather_y<<<GY, 256>>>(ecolR, rptr, t1, Y, du_inv, N_USERS);
        k_z_fused<<<GZ, 256>>>(erowC, cptr, Y, t1, t0, tn, di_inv, 2.f, -4.f, -1.f);
    }

    // out = D_i^{+1/2} Σ c_k T_k  (+ identity path for zero-degree items)
    k_finalize<<<dim3((N_ITEMS + 31) / 32, 2), dim3(32, 8)>>>(T, signal, outp,
                                                              fin_a, fin_b, C);
}